// round 8
// baseline (speedup 1.0000x reference)
#include <cuda_runtime.h>

#define BB 16
#define NN 127
#define SS 32
#define EE 16
#define VV 128
#define TT 128   // N+1
#define LL 128
#define XST 132  // xs row stride (conflict-free broadcasts)

// per-(b,t) hidden vectors handed from main -> tail
__device__ float g_hvec[BB * TT * EE];

__global__ __launch_bounds__(256, 6)
void memnet_main(const float* __restrict__ node_fts,
                 const float* __restrict__ edge_fts,
                 const float* __restrict__ graph_fts,
                 const float* __restrict__ adj_mat,
                 const float* __restrict__ query_biases,
                 const float* __restrict__ stories_biases,
                 const float* __restrict__ output_biases,
                 const float* __restrict__ memory_contents)
{
    __shared__ __align__(16) float obtV[VV * 20];   // output_biases, v-major, stride 20
    __shared__ unsigned int sidxw[TT * 8];          // packed u8 story indices [m][8 words]
    __shared__ float2 Qt[VV];                       // (Q0, Q1) per vocab id
    __shared__ float uvec[EE];
    __shared__ float logits[TT];
    __shared__ float probs[TT];
    __shared__ float lgpart[256];
    __shared__ __align__(16) float red0[8 * 16];
    __shared__ __align__(16) float red1[8 * 16];
    __shared__ float redp[8];
    __shared__ int qidx[SS];
    __shared__ unsigned char zrow[TT];
    __shared__ int nzlist[TT];
    __shared__ int warpcnt[4];
    __shared__ int nzcnt;
    __shared__ float wred[4];

    const int tid = threadIdx.x;
    const int bt = blockIdx.x;
    const int b = bt >> 7;
    const int t = bt & 127;

    // ---------------- A: adj flags + ballot (regs), query idx ----------------
    bool nz = false;
    int pos = 0;
    if (tid < TT) {
        if (t < NN && tid < NN) nz = (adj_mat[(b * NN + t) * NN + tid] != 0.f);
        zrow[tid] = nz ? 0 : 1;
        unsigned mask = __ballot_sync(0xFFFFFFFFu, nz);
        if ((tid & 31) == 0) warpcnt[tid >> 5] = __popc(mask);
        pos = __popc(mask & ((1u << (tid & 31)) - 1u));
    } else if (tid < 160) {
        int s = tid - 128;
        float qv = (t < NN) ? node_fts[(b * NN + t) * SS + s]
                            : graph_fts[b * SS + s];
        qidx[s] = min(max((int)qv, 0), VV - 1);
    }
    __syncthreads();

    // ---------------- B: nzlist, u vector, ob table (v-major) ----------------
    if (tid < TT) {
        int w = tid >> 5;
        int off = 0;
        #pragma unroll
        for (int i = 0; i < 4; i++) if (i < w) off += warpcnt[i];
        if (nz) nzlist[off + pos] = tid;
        if (tid == 0) nzcnt = warpcnt[0] + warpcnt[1] + warpcnt[2] + warpcnt[3];
    } else if (tid < 144) {
        // u[e] = sum_s qb[qidx_s, e] * enc(s,e), enc = 1 + (e-7)(s-15)/128
        int e = tid - 128;
        float ae = (float)(e - 7) * (1.f / 128.f);
        float acc = 0.f;
        #pragma unroll
        for (int s = 0; s < SS; s++) {
            int idx = qidx[s];
            float qv = (idx < VV - 1) ? query_biases[idx * EE + e] : 0.f;
            acc += qv * (1.f + ae * (float)(s - 15));
        }
        uvec[e] = acc;
    }
    for (int i = tid; i < VV * EE; i += 256) {
        int v = i >> 4, e = i & 15;
        obtV[v * 20 + e] = (v < VV - 1) ? output_biases[v * EE + e] : 0.f;
    }
    __syncthreads();

    const int K = nzcnt;

    // ---------------- C: stage edge rows (nonzero only) + Q tables + logit init ----------------
    for (int slot = tid; slot < K * 8; slot += 256) {
        int r = slot >> 3, j = slot & 7;
        int m = nzlist[r];
        float4 ef4 = ((const float4*)edge_fts)[((b * NN + t) * NN + m) * 8 + j];
        unsigned int w;
        w  = (unsigned int)min(max((int)ef4.x, 0), 127);
        w |= (unsigned int)min(max((int)ef4.y, 0), 127) << 8;
        w |= (unsigned int)min(max((int)ef4.z, 0), 127) << 16;
        w |= (unsigned int)min(max((int)ef4.w, 0), 127) << 24;
        sidxw[m * 8 + j] = w;
    }
    if (tid < VV) {
        int v = tid;
        float q0 = 0.f, q1 = 0.f;
        if (v < VV - 1) {
            #pragma unroll
            for (int e = 0; e < EE; e++) {
                float sv = stories_biases[v * EE + e];
                float ue = uvec[e];
                q0 += sv * ue;
                q1 += sv * ue * ((float)(e - 7) * (1.f / 128.f));
            }
        }
        Qt[v] = make_float2(q0, q1);
    } else {
        int m = tid - 128;
        float acc = 0.f;
        #pragma unroll
        for (int e = 0; e < EE; e++)
            acc += memory_contents[m * EE + e] * uvec[e];
        logits[m] = acc;
    }
    __syncthreads();

    // ---------------- D: pass-1 scalar gathers -> logit partials ----------------
    {
        int m = tid >> 1, h = tid & 1;
        float acc = 0.f;
        if (zrow[m]) {
            if (h == 0) acc = 32.f * Qt[0].x + 16.f * Qt[0].y;
        } else {
            #pragma unroll
            for (int sw = 0; sw < 4; sw++) {
                unsigned int w = sidxw[m * 8 + h * 4 + sw];
                #pragma unroll
                for (int k = 0; k < 4; k++) {
                    int idx = (w >> (8 * k)) & 255;
                    int s = (h * 4 + sw) * 4 + k;
                    float2 q = Qt[idx];
                    acc += q.x + (float)(s - 15) * q.y;
                }
            }
        }
        lgpart[tid] = acc;
    }
    __syncthreads();

    // ---------------- E: softmax (logits are tiny -> no max shift needed) ----------------
    if (tid < TT) {
        float lv = logits[tid] + lgpart[2 * tid] + lgpart[2 * tid + 1];
        float ev = __expf(lv);
        probs[tid] = ev;
        float sm = ev;
        #pragma unroll
        for (int o = 16; o; o >>= 1) sm += __shfl_xor_sync(0xFFFFFFFFu, sm, o);
        if ((tid & 31) == 0) wred[tid >> 5] = sm;
    }
    __syncthreads();
    if (tid < TT) {
        float inv = 1.f / (wred[0] + wred[1] + wred[2] + wred[3]);
        probs[tid] *= inv;
    }
    __syncthreads();

    // ---------------- F: pass-2 gathers, e-quad vectorized ----------------
    // lane = 4*p + eq : pair p in 0..7 handles s = it*8+p, eq selects 4 e's (float4).
    {
        int w = tid >> 5, lane = tid & 31;
        int p = lane >> 2, eq = lane & 3;
        float4 a0 = make_float4(0.f, 0.f, 0.f, 0.f);
        float4 a1 = make_float4(0.f, 0.f, 0.f, 0.f);
        float accp = 0.f;
        for (int r = w; r < K; r += 8) {
            int m = nzlist[r];
            float pm = probs[m];
            if (lane == 0) accp += pm;
            #pragma unroll
            for (int it = 0; it < 4; it++) {
                int s = it * 8 + p;
                unsigned int wd = sidxw[m * 8 + (s >> 2)];
                int idx = (wd >> (8 * (s & 3))) & 255;
                const float4 val = *(const float4*)&obtV[idx * 20 + eq * 4];
                float c1 = pm * (float)(s - 15);
                a0.x = fmaf(val.x, pm, a0.x);
                a0.y = fmaf(val.y, pm, a0.y);
                a0.z = fmaf(val.z, pm, a0.z);
                a0.w = fmaf(val.w, pm, a0.w);
                a1.x = fmaf(val.x, c1, a1.x);
                a1.y = fmaf(val.y, c1, a1.y);
                a1.z = fmaf(val.z, c1, a1.z);
                a1.w = fmaf(val.w, c1, a1.w);
            }
        }
        // reduce across the 8 p-lanes sharing each eq (xor 16, 8, 4)
        #pragma unroll
        for (int o = 16; o >= 4; o >>= 1) {
            a0.x += __shfl_xor_sync(0xFFFFFFFFu, a0.x, o);
            a0.y += __shfl_xor_sync(0xFFFFFFFFu, a0.y, o);
            a0.z += __shfl_xor_sync(0xFFFFFFFFu, a0.z, o);
            a0.w += __shfl_xor_sync(0xFFFFFFFFu, a0.w, o);
            a1.x += __shfl_xor_sync(0xFFFFFFFFu, a1.x, o);
            a1.y += __shfl_xor_sync(0xFFFFFFFFu, a1.y, o);
            a1.z += __shfl_xor_sync(0xFFFFFFFFu, a1.z, o);
            a1.w += __shfl_xor_sync(0xFFFFFFFFu, a1.w, o);
        }
        if (lane < 4) {
            *(float4*)&red0[w * 16 + eq * 4] = a0;
            *(float4*)&red1[w * 16 + eq * 4] = a1;
        }
        if (lane == 0) redp[w] = accp;
    }
    __syncthreads();

    // ---------------- G: combine -> hvec, write to global ----------------
    if (tid < EE) {
        int e = tid;
        float O0 = 0.f, O1 = 0.f, sp = 0.f;
        #pragma unroll
        for (int w = 0; w < 8; w++) {
            O0 += red0[w * 16 + e];
            O1 += red1[w * 16 + e];
            sp += redp[w];
        }
        float Z = 1.f - sp;                  // prob mass on zero rows
        float ob0 = obtV[e];                 // table row for idx 0
        O0 += Z * 32.f * ob0;
        O1 += Z * 16.f * ob0;
        float ae = (float)(e - 7) * (1.f / 128.f);
        g_hvec[bt * EE + e] = uvec[e] + O0 + ae * O1;
    }
}

// Tail: x = relu(h @ W_out); ret = x @ W_fin; out = ret[t] + ret[graph].
// 128 CTAs, each handles 16 rows of one batch + (redundantly) that batch's graph row.
// Register-tiled: each thread owns float4 of v x 2 rows; wfin[l][v] in smem so a
// warp's load is one 128B broadcast-dedup'd wavefront; xs stride 132 -> conflict-free.
__global__ __launch_bounds__(256)
void memnet_tail(const float* __restrict__ W_out,
                 const float* __restrict__ W_fin,
                 float* __restrict__ out)
{
    extern __shared__ __align__(16) float smf[];
    float* wout = smf;                  // 16*128  = 2048
    float* wfin = wout + EE * LL;       // 128*128 = 16384  (layout [l][v])
    float* hs   = wfin + LL * VV;       // 17*16   = 272
    float* xs   = hs + 17 * EE;         // 17*132  = 2244
    float* rg   = xs + 17 * XST;        // 128
    float* lgp  = rg + VV;              // 256

    const int tid = threadIdx.x;
    const int cta = blockIdx.x;
    const int b = cta >> 3;
    const int chunk = cta & 7;

    for (int i = tid; i < EE * LL; i += 256) wout[i] = W_out[i];
    for (int i = tid; i < (LL * VV) / 4; i += 256)
        ((float4*)wfin)[i] = ((const float4*)W_fin)[i];
    for (int i = tid; i < 17 * EE; i += 256) {
        int r = i >> 4, e = i & 15;
        int t = (r < 16) ? chunk * 16 + r : 127;
        hs[i] = g_hvec[(b * TT + t) * EE + e];
    }
    __syncthreads();

    // xs[r][l] = relu(sum_e hs[r][e] * wout[e][l]),  17*128 outputs
    for (int i = tid; i < 17 * LL; i += 256) {
        int r = i >> 7, l = i & 127;
        float acc = 0.f;
        #pragma unroll
        for (int e = 0; e < EE; e++) acc += hs[r * EE + e] * wout[e * LL + l];
        xs[r * XST + l] = fmaxf(acc, 0.f);
    }
    __syncthreads();

    // graph-row ret -> rg
    {
        int v = tid & 127, half = tid >> 7;
        float acc = 0.f;
        #pragma unroll
        for (int l = half * 64; l < half * 64 + 64; l++)
            acc += xs[16 * XST + l] * wfin[l * VV + v];
        lgp[tid] = acc;
    }
    __syncthreads();
    if (tid < VV) rg[tid] = lgp[tid] + lgp[128 + tid];
    __syncthreads();

    // main GEMM: 16 rows x 128 v, register-tiled
    {
        int w = tid >> 5, lane = tid & 31;
        int vq = (w & 3) * 8 + (lane & 7);        // float4 column group, v = 4*vq
        int rp = (w >> 2) * 4 + (lane >> 3);      // 0..7
        int r0 = rp * 2, r1 = r0 + 1;
        const float4* wf4 = (const float4*)wfin;
        float4 a0 = make_float4(0.f, 0.f, 0.f, 0.f);
        float4 a1 = make_float4(0.f, 0.f, 0.f, 0.f);
        #pragma unroll 4
        for (int l = 0; l < LL; l++) {
            float4 wv = wf4[l * 32 + vq];
            float x0 = xs[r0 * XST + l];
            float x1 = xs[r1 * XST + l];
            a0.x = fmaf(wv.x, x0, a0.x);
            a0.y = fmaf(wv.y, x0, a0.y);
            a0.z = fmaf(wv.z, x0, a0.z);
            a0.w = fmaf(wv.w, x0, a0.w);
            a1.x = fmaf(wv.x, x1, a1.x);
            a1.y = fmaf(wv.y, x1, a1.y);
            a1.z = fmaf(wv.z, x1, a1.z);
            a1.w = fmaf(wv.w, x1, a1.w);
        }
        float4 rgv = *(float4*)&rg[vq * 4];
        a0.x += rgv.x; a0.y += rgv.y; a0.z += rgv.z; a0.w += rgv.w;
        a1.x += rgv.x; a1.y += rgv.y; a1.z += rgv.z; a1.w += rgv.w;
        int t0 = chunk * 16 + r0;
        int t1 = chunk * 16 + r1;
        if (t0 < NN) *(float4*)&out[(b * NN + t0) * VV + vq * 4] = a0;
        if (t1 < NN) *(float4*)&out[(b * NN + t1) * VV + vq * 4] = a1;
    }
}

extern "C" void kernel_launch(void* const* d_in, const int* in_sizes, int n_in,
                              void* d_out, int out_size)
{
    (void)in_sizes; (void)n_in; (void)out_size;
    const float* node_fts        = (const float*)d_in[0];
    const float* edge_fts        = (const float*)d_in[1];
    const float* graph_fts       = (const float*)d_in[2];
    const float* adj_mat         = (const float*)d_in[3];
    // d_in[4] hidden (unused), d_in[5] enc (computed analytically, exact)
    const float* query_biases    = (const float*)d_in[6];
    const float* stories_biases  = (const float*)d_in[7];
    const float* output_biases   = (const float*)d_in[8];
    const float* memory_contents = (const float*)d_in[9];
    // d_in[10] W_int unused (num_hops == 1)
    const float* W_out           = (const float*)d_in[11];
    const float* W_fin           = (const float*)d_in[12];

    const int tail_smem = (EE * LL + LL * VV + 17 * EE + 17 * XST + VV + 256) * (int)sizeof(float);
    cudaFuncSetAttribute(memnet_tail, cudaFuncAttributeMaxDynamicSharedMemorySize, tail_smem);

    memnet_main<<<BB * TT, 256>>>(node_fts, edge_fts, graph_fts, adj_mat,
                                  query_biases, stories_biases, output_biases,
                                  memory_contents);
    memnet_tail<<<BB * 8, 256, tail_smem>>>(W_out, W_fin, (float*)d_out);
}

// round 9
// speedup vs baseline: 1.0891x; 1.0891x over previous
#include <cuda_runtime.h>

#define BB 16
#define NN 127
#define SS 32
#define EE 16
#define VV 128
#define TT 128   // N+1
#define LL 128
#define XST 132  // xs row stride

// per-(b,t) hidden vectors handed from main -> tail
__device__ float g_hvec[BB * TT * EE];

__global__ __launch_bounds__(256, 8)
void memnet_main(const float* __restrict__ node_fts,
                 const float* __restrict__ edge_fts,
                 const float* __restrict__ graph_fts,
                 const float* __restrict__ adj_mat,
                 const float* __restrict__ query_biases,
                 const float* __restrict__ stories_biases,
                 const float* __restrict__ output_biases,
                 const float* __restrict__ memory_contents)
{
    __shared__ float obt[EE * 129];          // output_biases, e-major, padded
    __shared__ unsigned int sidxw[TT * 8];   // packed u8 story indices [m][8 words]
    __shared__ float2 Qt[VV];                // (Q0, Q1) per vocab id
    __shared__ float uvec[EE];
    __shared__ float logits[TT];
    __shared__ float probs[TT];
    __shared__ float lgpart[256];
    __shared__ float red0[16 * 16];
    __shared__ float red1[16 * 16];
    __shared__ float redp[16];
    __shared__ int qidx[SS];
    __shared__ unsigned char zrow[TT];
    __shared__ int nzlist[TT];
    __shared__ int warpcnt[4];
    __shared__ int nzcnt;
    __shared__ float wred[4];

    const int tid = threadIdx.x;
    const int bt = blockIdx.x;
    const int b = bt >> 7;
    const int t = bt & 127;

    // ---------------- A: adj flags + ballot (regs), query idx ----------------
    bool nz = false;
    int pos = 0;
    if (tid < TT) {
        if (t < NN && tid < NN) nz = (adj_mat[(b * NN + t) * NN + tid] != 0.f);
        zrow[tid] = nz ? 0 : 1;
        unsigned mask = __ballot_sync(0xFFFFFFFFu, nz);
        if ((tid & 31) == 0) warpcnt[tid >> 5] = __popc(mask);
        pos = __popc(mask & ((1u << (tid & 31)) - 1u));
    } else if (tid < 160) {
        int s = tid - 128;
        float qv = (t < NN) ? node_fts[(b * NN + t) * SS + s]
                            : graph_fts[b * SS + s];
        qidx[s] = min(max((int)qv, 0), VV - 1);
    }
    __syncthreads();

    // ---------------- B: nzlist, u vector, ob table ----------------
    if (tid < TT) {
        int w = tid >> 5;
        int off = 0;
        #pragma unroll
        for (int i = 0; i < 4; i++) if (i < w) off += warpcnt[i];
        if (nz) nzlist[off + pos] = tid;
        if (tid == 0) nzcnt = warpcnt[0] + warpcnt[1] + warpcnt[2] + warpcnt[3];
    } else if (tid < 144) {
        // u[e] = sum_s qb[qidx_s, e] * enc(s,e), enc = 1 + (e-7)(s-15)/128
        int e = tid - 128;
        float ae = (float)(e - 7) * (1.f / 128.f);
        float acc = 0.f;
        #pragma unroll
        for (int s = 0; s < SS; s++) {
            int idx = qidx[s];
            float qv = (idx < VV - 1) ? query_biases[idx * EE + e] : 0.f;
            acc += qv * (1.f + ae * (float)(s - 15));
        }
        uvec[e] = acc;
    }
    for (int i = tid; i < VV * EE; i += 256) {
        int v = i >> 4, e = i & 15;
        obt[e * 129 + v] = (v < VV - 1) ? output_biases[v * EE + e] : 0.f;
    }
    __syncthreads();

    const int K = nzcnt;

    // ---------------- C: stage edge rows (nonzero only) + Q tables + logit init ----------------
    for (int slot = tid; slot < K * 8; slot += 256) {
        int r = slot >> 3, j = slot & 7;
        int m = nzlist[r];
        float4 ef4 = ((const float4*)edge_fts)[((b * NN + t) * NN + m) * 8 + j];
        unsigned int w;
        w  = (unsigned int)min(max((int)ef4.x, 0), 127);
        w |= (unsigned int)min(max((int)ef4.y, 0), 127) << 8;
        w |= (unsigned int)min(max((int)ef4.z, 0), 127) << 16;
        w |= (unsigned int)min(max((int)ef4.w, 0), 127) << 24;
        sidxw[m * 8 + j] = w;
    }
    if (tid < VV) {
        int v = tid;
        float q0 = 0.f, q1 = 0.f;
        if (v < VV - 1) {
            #pragma unroll
            for (int e = 0; e < EE; e++) {
                float sv = stories_biases[v * EE + e];
                float ue = uvec[e];
                q0 += sv * ue;
                q1 += sv * ue * ((float)(e - 7) * (1.f / 128.f));
            }
        }
        Qt[v] = make_float2(q0, q1);
    } else {
        int m = tid - 128;
        float acc = 0.f;
        #pragma unroll
        for (int e = 0; e < EE; e++)
            acc += memory_contents[m * EE + e] * uvec[e];
        logits[m] = acc;
    }
    __syncthreads();

    // ---------------- D: pass-1 scalar gathers -> logit partials ----------------
    {
        int m = tid >> 1, h = tid & 1;
        float acc = 0.f;
        if (zrow[m]) {
            if (h == 0) acc = 32.f * Qt[0].x + 16.f * Qt[0].y;
        } else {
            #pragma unroll
            for (int sw = 0; sw < 4; sw++) {
                unsigned int w = sidxw[m * 8 + h * 4 + sw];
                #pragma unroll
                for (int k = 0; k < 4; k++) {
                    int idx = (w >> (8 * k)) & 255;
                    int s = (h * 4 + sw) * 4 + k;
                    float2 q = Qt[idx];
                    acc += q.x + (float)(s - 15) * q.y;
                }
            }
        }
        lgpart[tid] = acc;
    }
    __syncthreads();

    // ---------------- E: softmax (logits are tiny -> no max shift needed) ----------------
    if (tid < TT) {
        float lv = logits[tid] + lgpart[2 * tid] + lgpart[2 * tid + 1];
        float ev = __expf(lv);
        probs[tid] = ev;
        float sm = ev;
        #pragma unroll
        for (int o = 16; o; o >>= 1) sm += __shfl_xor_sync(0xFFFFFFFFu, sm, o);
        if ((tid & 31) == 0) wred[tid >> 5] = sm;
    }
    __syncthreads();
    if (tid < TT) {
        float inv = 1.f / (wred[0] + wred[1] + wred[2] + wred[3]);
        probs[tid] *= inv;
    }
    __syncthreads();

    // ---------------- F: pass-2 row gathers (lane = e, half-warp per row) ----------------
    {
        int hw = tid >> 4, e = tid & 15;
        float acc0 = 0.f, acc1 = 0.f, accp = 0.f;
        for (int r = hw; r < K; r += 16) {
            int m = nzlist[r];
            float pm = probs[m];
            accp += pm;
            float r0 = 0.f, r1 = 0.f;
            #pragma unroll
            for (int sw = 0; sw < 8; sw++) {
                unsigned int w = sidxw[m * 8 + sw];
                #pragma unroll
                for (int k = 0; k < 4; k++) {
                    int idx = (w >> (8 * k)) & 255;
                    float val = obt[e * 129 + idx];
                    int s = sw * 4 + k;
                    r0 += val;
                    r1 += (float)(s - 15) * val;
                }
            }
            acc0 += pm * r0;
            acc1 += pm * r1;
        }
        red0[hw * 16 + e] = acc0;
        red1[hw * 16 + e] = acc1;
        if (e == 0) redp[hw] = accp;
    }
    __syncthreads();

    // ---------------- G: combine -> hvec, write to global ----------------
    if (tid < EE) {
        int e = tid;
        float O0 = 0.f, O1 = 0.f, sp = 0.f;
        #pragma unroll
        for (int hw = 0; hw < 16; hw++) {
            O0 += red0[hw * 16 + e];
            O1 += red1[hw * 16 + e];
            sp += redp[hw];
        }
        float Z = 1.f - sp;                  // prob mass on zero rows
        float ob0 = obt[e * 129];            // table row for idx 0
        O0 += Z * 32.f * ob0;
        O1 += Z * 16.f * ob0;
        float ae = (float)(e - 7) * (1.f / 128.f);
        g_hvec[bt * EE + e] = uvec[e] + O0 + ae * O1;
    }
}

// Tail v3: x = relu(h @ W_out); ret = x @ W_fin; out = ret[t] + ret[graph].
// 256 CTAs (8 node rows + graph row each) -> fills all SMs, ~2 CTAs/SM.
// W_fin is read straight from L1/L2 via coalesced LDG.128 (16MB L2 total);
// smem only ~13KB (wout + hs + xs). Per warp: rp constant -> xs reads are
// single-address broadcasts; each wfin load feeds 8 FMAs (own row + graph row).
__global__ __launch_bounds__(256, 4)
void memnet_tail(const float* __restrict__ W_out,
                 const float* __restrict__ W_fin,
                 float* __restrict__ out)
{
    __shared__ float wout[EE * LL];     // 16*128
    __shared__ float hs[9 * EE];        // 9 rows (8 node + graph)
    __shared__ float xs[9 * XST];

    const int tid = threadIdx.x;
    const int cta = blockIdx.x;
    const int b = cta >> 4;
    const int chunk = cta & 15;         // 8-row chunk

    for (int i = tid; i < EE * LL; i += 256) wout[i] = W_out[i];
    if (tid < 9 * EE) {
        int r = tid >> 4, e = tid & 15;
        int t = (r < 8) ? chunk * 8 + r : 127;
        hs[tid] = g_hvec[(b * TT + t) * EE + e];
    }
    __syncthreads();

    // xs[r][l] = relu(sum_e hs[r][e] * wout[e][l]),  9*128 outputs
    for (int i = tid; i < 9 * LL; i += 256) {
        int r = (i >> 7), l = i & 127;
        float acc = 0.f;
        #pragma unroll
        for (int e = 0; e < EE; e++) acc += hs[r * EE + e] * wout[e * LL + l];
        xs[r * XST + l] = fmaxf(acc, 0.f);
    }
    __syncthreads();

    // ret rows + graph add: thread = (rp 0..7) x (vq 0..31); graph acc fused.
    {
        int vq = tid & 31, rp = tid >> 5;
        const float4* wf4 = (const float4*)W_fin;
        float4 a  = make_float4(0.f, 0.f, 0.f, 0.f);
        float4 ag = make_float4(0.f, 0.f, 0.f, 0.f);
        #pragma unroll 8
        for (int l = 0; l < LL; l++) {
            float4 wv = wf4[l * 32 + vq];
            float x0 = xs[rp * XST + l];
            float xg = xs[8 * XST + l];
            a.x  = fmaf(wv.x, x0, a.x);
            a.y  = fmaf(wv.y, x0, a.y);
            a.z  = fmaf(wv.z, x0, a.z);
            a.w  = fmaf(wv.w, x0, a.w);
            ag.x = fmaf(wv.x, xg, ag.x);
            ag.y = fmaf(wv.y, xg, ag.y);
            ag.z = fmaf(wv.z, xg, ag.z);
            ag.w = fmaf(wv.w, xg, ag.w);
        }
        a.x += ag.x; a.y += ag.y; a.z += ag.z; a.w += ag.w;
        int t = chunk * 8 + rp;
        if (t < NN) *(float4*)&out[(b * NN + t) * VV + vq * 4] = a;
    }
}

extern "C" void kernel_launch(void* const* d_in, const int* in_sizes, int n_in,
                              void* d_out, int out_size)
{
    (void)in_sizes; (void)n_in; (void)out_size;
    const float* node_fts        = (const float*)d_in[0];
    const float* edge_fts        = (const float*)d_in[1];
    const float* graph_fts       = (const float*)d_in[2];
    const float* adj_mat         = (const float*)d_in[3];
    // d_in[4] hidden (unused), d_in[5] enc (computed analytically, exact)
    const float* query_biases    = (const float*)d_in[6];
    const float* stories_biases  = (const float*)d_in[7];
    const float* output_biases   = (const float*)d_in[8];
    const float* memory_contents = (const float*)d_in[9];
    // d_in[10] W_int unused (num_hops == 1)
    const float* W_out           = (const float*)d_in[11];
    const float* W_fin           = (const float*)d_in[12];

    memnet_main<<<BB * TT, 256>>>(node_fts, edge_fts, graph_fts, adj_mat,
                                  query_biases, stories_biases, output_biases,
                                  memory_contents);
    memnet_tail<<<BB * 16, 256>>>(W_out, W_fin, (float*)d_out);
}